// round 12
// baseline (speedup 1.0000x reference)
#include <cuda_runtime.h>
#include <cuda_bf16.h>
#include <cstdint>

#define SEQ     512
#define NBATCH  256
#define NSTATE  1024
#define NOUT    256
#define ALPHA   0.1f
#define OMALPHA 0.9f

#define NCTA 128
#define NTHR 512
#define BM 32
#define BN 64

// smem strides in bf16 elems; stride*2 mod 128 = 16 -> conflict-free LDSM
#define WR_STR 1032
#define WO_STR 1032
#define TH_STR 264

#define SMEM_WR   (64 * WR_STR)          // bf16 elems
#define CH_ELEM   (32 * TH_STR)          // one chunk buffer
#define SMEM_TH   (4 * CH_ELEM)          // 4 resident chunks
#define REDD_F    (8 * 512)              // D partial slots (floats)
#define REDC_F    (8 * 256)              // C partial slots (floats)
#define SMEM_BYTES ((SMEM_WR + SMEM_TH) * 2 + (REDD_F + REDC_F) * 4 + 64)
#define CH_B      (CH_ELEM * 2)          // chunk bytes in smem
#define CHUNK_BYTES 16384                // 32 rows x 512B payload

__device__ __align__(16) __nv_bfloat16 g_th[2][NBATCH * NSTATE];
__device__ unsigned g_flags[NCTA * 32];  // one flag per 128B

__device__ __forceinline__ float tanh_f(float v) {
    float r; asm("tanh.approx.f32 %0, %1;" : "=f"(r) : "f"(v)); return r;
}
__device__ __forceinline__ unsigned pack2(float a, float b) {
    __nv_bfloat162 t = __floats2bfloat162_rn(a, b);
    return *reinterpret_cast<unsigned*>(&t);
}
__device__ __forceinline__ void stcg_u32(void* p, unsigned v) {
    asm volatile("st.global.cg.b32 [%0], %1;" :: "l"(p), "r"(v));
}
__device__ __forceinline__ void ldsm4(unsigned r[4], unsigned addr) {
    asm volatile("ldmatrix.sync.aligned.m8n8.x4.shared.b16 {%0,%1,%2,%3}, [%4];"
                 : "=r"(r[0]), "=r"(r[1]), "=r"(r[2]), "=r"(r[3]) : "r"(addr));
}
__device__ __forceinline__ void mma16816(float c[4], const unsigned a[4], const unsigned b[2]) {
    asm volatile(
        "mma.sync.aligned.m16n8k16.row.col.f32.bf16.bf16.f32 "
        "{%0,%1,%2,%3},{%4,%5,%6,%7},{%8,%9},{%0,%1,%2,%3};"
        : "+f"(c[0]), "+f"(c[1]), "+f"(c[2]), "+f"(c[3])
        : "r"(a[0]), "r"(a[1]), "r"(a[2]), "r"(a[3]), "r"(b[0]), "r"(b[1]));
}

__device__ __forceinline__ void mbar_init(unsigned mbar, unsigned count) {
    asm volatile("mbarrier.init.shared.b64 [%0], %1;" :: "r"(mbar), "r"(count));
}
__device__ __forceinline__ void mbar_expect_tx(unsigned mbar, unsigned bytes) {
    asm volatile("mbarrier.arrive.expect_tx.shared.b64 _, [%0], %1;"
                 :: "r"(mbar), "r"(bytes) : "memory");
}
__device__ __forceinline__ void mbar_wait(unsigned mbar, unsigned parity) {
    asm volatile(
        "{\n\t.reg .pred P1;\n\t"
        "LAB_W_%=:\n\t"
        "mbarrier.try_wait.parity.acquire.cta.shared::cta.b64 P1, [%0], %1, 0x989680;\n\t"
        "@P1 bra LAB_D_%=;\n\t"
        "bra LAB_W_%=;\n\t"
        "LAB_D_%=:\n\t}"
        :: "r"(mbar), "r"(parity) : "memory");
}
__device__ __forceinline__ void bulk_ldg(unsigned dst_smem, const void* src,
                                         unsigned bytes, unsigned mbar) {
    asm volatile(
        "cp.async.bulk.shared::cta.global.mbarrier::complete_tx::bytes [%0], [%1], %2, [%3];"
        :: "r"(dst_smem), "l"(src), "r"(bytes), "r"(mbar) : "memory");
}

// 16-CTA group barrier on monotone per-CTA counters (replay-safe).
__device__ __forceinline__ void gbar(int cta, int grp, unsigned target) {
    __syncthreads();
    if (threadIdx.x == 0)
        asm volatile("st.release.gpu.global.b32 [%0], %1;"
                     :: "l"(g_flags + cta * 32), "r"(target) : "memory");
    if (threadIdx.x < 16) {
        unsigned v;
        const unsigned* f = g_flags + (grp * 16 + threadIdx.x) * 32;
        do {
            asm volatile("ld.acquire.gpu.global.b32 %0, [%1];"
                         : "=r"(v) : "l"(f) : "memory");
        } while (v < target);
    }
    __syncthreads();
}

__global__ void __launch_bounds__(NTHR, 1)
rnn_scan_kernel(const float* __restrict__ x, const float* __restrict__ h_init,
                const float* __restrict__ w_r, const float* __restrict__ b_r,
                const float* __restrict__ w_o, const float* __restrict__ b_o,
                float* __restrict__ out)
{
    extern __shared__ char smem_raw[];
    __nv_bfloat16* wr_s = (__nv_bfloat16*)smem_raw;
    __nv_bfloat16* th_s = wr_s + SMEM_WR;     // 4 chunk buffers (w_o staging in prologue)
    float*         redD = (float*)(th_s + SMEM_TH);      // 8 x 512
    float*         redC = redD + REDD_F;                 // 8 x 256
    unsigned long long* mbars = (unsigned long long*)(redC + REDC_F);  // 4 mbarriers
    unsigned*      s_base = (unsigned*)(mbars + 4);

    const int cta = blockIdx.x, tid = threadIdx.x;
    const int wid = tid >> 5, lane = tid & 31;
    const int g = lane >> 2, tg = lane & 3;
    const int grp = cta >> 4;
    const int wc = wid & 7;        // C-tile warp slot (both halves)
    const int hi = wid >> 3;       // 0 = low warps (K chunks 0,1), 1 = high (owners, 2,3)

    const int row0 = grp * BM;
    const int col0 = (cta & 15) * BN;
    const int wm = (wc >> 2) * 16, wn = (wc & 3) * 16;
    const int r0 = row0 + wm + g, r1 = r0 + 8;
    const int cb = col0 + wn + 2 * tg;
    const int nb2 = (cta & 15) * 16;

    const unsigned th_u32 = (unsigned)__cvta_generic_to_shared(th_s);
    const unsigned wr_u32 = (unsigned)__cvta_generic_to_shared(wr_s);
    const unsigned mb_u32 = (unsigned)__cvta_generic_to_shared(mbars);
    const int l15 = lane & 15, lhi = lane >> 4;
    const unsigned aA_off = ((wm + l15) * TH_STR + lhi * 8) * 2;
    const unsigned bA_off = ((wn + l15) * WR_STR + lhi * 8) * 2;
    const unsigned aB_off = (l15 * TH_STR + lhi * 8) * 2;
    const unsigned bB_off = (l15 * WO_STR + lhi * 8) * 2;
    const int klD = wid * 16;      // phase-D K slice within each 256-chunk

    // ---- prologue: w_r -> smem (once) ----
    for (int i = tid; i < 64 * 256; i += NTHR) {
        int n = i >> 8, c4 = i & 255;
        float4 v = ((const float4*)(w_r + (col0 + n) * NSTATE))[c4];
        __nv_bfloat16* d = wr_s + n * WR_STR + c4 * 4;
        d[0] = __float2bfloat16(v.x); d[1] = __float2bfloat16(v.y);
        d[2] = __float2bfloat16(v.z); d[3] = __float2bfloat16(v.w);
    }
    // stage w_o in th_s, pull fragments into registers
    for (int i = tid; i < 16 * 256; i += NTHR) {
        int n = i >> 8, c4 = i & 255;
        float4 v = ((const float4*)(w_o + (nb2 + n) * NSTATE))[c4];
        __nv_bfloat16* d = th_s + n * WO_STR + c4 * 4;
        d[0] = __float2bfloat16(v.x); d[1] = __float2bfloat16(v.y);
        d[2] = __float2bfloat16(v.z); d[3] = __float2bfloat16(v.w);
    }
    __syncthreads();
    unsigned bD[16];   // w_o fragments: 4 chunks x (m8n8)x4, this warp's 16 K-cols
    #pragma unroll
    for (int ch = 0; ch < 4; ch++)
        ldsm4(&bD[ch * 4], th_u32 + bB_off + (ch * 256 + klD) * 2);
    __syncthreads();

    float br[4] = { b_r[cb], b_r[cb + 1], b_r[cb + 8], b_r[cb + 9] };
    const float bo = b_o[nb2 + (tid & 15)];
    float h[8];
    h[0] = h_init[r0 * NSTATE + cb];     h[1] = h_init[r0 * NSTATE + cb + 1];
    h[2] = h_init[r1 * NSTATE + cb];     h[3] = h_init[r1 * NSTATE + cb + 1];
    h[4] = h_init[r0 * NSTATE + cb + 8]; h[5] = h_init[r0 * NSTATE + cb + 9];
    h[6] = h_init[r1 * NSTATE + cb + 8]; h[7] = h_init[r1 * NSTATE + cb + 9];

    if (hi == 1) {   // owners publish tanh(h0)
        stcg_u32(&g_th[0][r0 * NSTATE + cb],     pack2(tanh_f(h[0]), tanh_f(h[1])));
        stcg_u32(&g_th[0][r1 * NSTATE + cb],     pack2(tanh_f(h[2]), tanh_f(h[3])));
        stcg_u32(&g_th[0][r0 * NSTATE + cb + 8], pack2(tanh_f(h[4]), tanh_f(h[5])));
        stcg_u32(&g_th[0][r1 * NSTATE + cb + 8], pack2(tanh_f(h[6]), tanh_f(h[7])));
    }

    if (tid == 0) {
        *s_base = g_flags[cta * 32];
        mbar_init(mb_u32,      1);
        mbar_init(mb_u32 + 8,  1);
        mbar_init(mb_u32 + 16, 1);
        mbar_init(mb_u32 + 24, 1);
    }
    __syncthreads();
    const unsigned base = *s_base;
    unsigned bar = 1;
    unsigned par = 0;

    gbar(cta, grp, base + bar); bar++;

    // issue all 4 chunks of iteration 0
    if (wid < 4) {
        const unsigned mb = mb_u32 + wid * 8;
        if (lane == 0) mbar_expect_tx(mb, CHUNK_BYTES);
        __syncwarp();
        bulk_ldg(th_u32 + wid * CH_B + lane * (TH_STR * 2),
                 g_th[0] + (row0 + lane) * NSTATE + wid * 256, 512, mb);
    }

    // ---- fused scan: iter i consumes tanh(h_i); C -> h_{i+1}; D -> err_{i-1} ----
    for (int i = 0; i <= SEQ; i++) {
        const bool doC = (i < SEQ);
        const bool doD = (i > 0);

        float C0[4] = {0,0,0,0}, C1[4] = {0,0,0,0};
        float D[4][4];
        #pragma unroll
        for (int q = 0; q < 4; q++) { D[q][0]=0; D[q][1]=0; D[q][2]=0; D[q][3]=0; }

        float xv0 = 0.f; int oi0 = 0;
        if (doD) {
            oi0 = ((i - 1) * NBATCH + row0 + (tid & 511) / 16 % 32) * NOUT;  // placeholder; real below
            oi0 = ((i - 1) * NBATCH + row0 + (tid >> 4 & 31)) * NOUT + nb2 + (tid & 15);
            xv0 = __ldg(x + oi0);
        }

        #pragma unroll
        for (int ch = 0; ch < 4; ch++) {
            mbar_wait(mb_u32 + ch * 8, par);
            const unsigned cur = th_u32 + ch * CH_B;
            if (doC && ((ch >> 1) == hi)) {   // this half's K-chunks
                const unsigned abase = cur + aA_off;
                const unsigned bbase = wr_u32 + bA_off + ch * 512;
                #pragma unroll
                for (int kk = 0; kk < 16; kk++) {
                    unsigned a[4], b[4];
                    ldsm4(a, abase + kk * 32);
                    ldsm4(b, bbase + kk * 32);
                    unsigned b0[2] = { b[0], b[2] }, b1[2] = { b[1], b[3] };
                    mma16816(C0, a, b0);
                    mma16816(C1, a, b1);
                }
                if (hi == 0 && ch == 1) {     // low half: hand off C partial
                    float* rc = redC + wc * 256 + lane * 8;
                    #pragma unroll
                    for (int j = 0; j < 4; j++) { rc[j] = C0[j]; rc[4 + j] = C1[j]; }
                }
            }
            if (doD) {
                unsigned a0[4], a1[4];
                ldsm4(a0, cur + aB_off + klD * 2);
                ldsm4(a1, cur + aB_off + klD * 2 + 16 * TH_STR * 2);
                const unsigned* b = &bD[ch * 4];
                unsigned b0[2] = { b[0], b[2] }, b1[2] = { b[1], b[3] };
                mma16816(D[0], a0, b0);
                mma16816(D[1], a0, b1);
                mma16816(D[2], a1, b0);
                mma16816(D[3], a1, b1);
            }
        }
        par ^= 1;

        // stage1: high warps park their D partials
        if (doD && hi == 1) {
            float* rw = redD + wc * 512;
            #pragma unroll
            for (int q = 0; q < 4; q++) {
                int mi = q >> 1, ni = q & 1;
                #pragma unroll
                for (int j = 0; j < 4; j++)
                    rw[(mi * 16 + g + ((j >> 1) << 3)) * 16 + ni * 8 + 2 * tg + (j & 1)] = D[q][j];
            }
        }
        __syncthreads();   // redC + redD stage1 visible

        if (doC && hi == 1) {   // owners: fold partner C, update h, publish
            const float* rc = redC + wc * 256 + lane * 8;
            #pragma unroll
            for (int j = 0; j < 4; j++) {
                h[j]     = OMALPHA * h[j]     + ALPHA * (C0[j] + rc[j]     + br[j & 1]);
                h[4 + j] = OMALPHA * h[4 + j] + ALPHA * (C1[j] + rc[4 + j] + br[2 + (j & 1)]);
            }
            __nv_bfloat16* thw = g_th[(i + 1) & 1];
            stcg_u32(&thw[r0 * NSTATE + cb],     pack2(tanh_f(h[0]), tanh_f(h[1])));
            stcg_u32(&thw[r1 * NSTATE + cb],     pack2(tanh_f(h[2]), tanh_f(h[3])));
            stcg_u32(&thw[r0 * NSTATE + cb + 8], pack2(tanh_f(h[4]), tanh_f(h[5])));
            stcg_u32(&thw[r1 * NSTATE + cb + 8], pack2(tanh_f(h[6]), tanh_f(h[7])));
        }
        // stage2 (parallel with owners): low warps fold partner D, store combined
        if (doD && hi == 0) {
            float* rw = redD + wc * 512;
            float acc[16];
            #pragma unroll
            for (int q = 0; q < 4; q++) {
                int mi = q >> 1, ni = q & 1;
                #pragma unroll
                for (int j = 0; j < 4; j++) {
                    int idx = (mi * 16 + g + ((j >> 1) << 3)) * 16 + ni * 8 + 2 * tg + (j & 1);
                    acc[q * 4 + j] = D[q][j] + rw[idx];
                }
            }
            __syncwarp();
            #pragma unroll
            for (int q = 0; q < 4; q++) {
                int mi = q >> 1, ni = q & 1;
                #pragma unroll
                for (int j = 0; j < 4; j++)
                    rw[(mi * 16 + g + ((j >> 1) << 3)) * 16 + ni * 8 + 2 * tg + (j & 1)] = acc[q * 4 + j];
            }
        }

        if (doC) {
            gbar(cta, grp, base + bar); bar++;
            // issue all 4 chunks of the next iteration immediately
            if (wid < 4) {
                const unsigned mb = mb_u32 + wid * 8;
                if (lane == 0) mbar_expect_tx(mb, CHUNK_BYTES);
                __syncwarp();
                bulk_ldg(th_u32 + wid * CH_B + lane * (TH_STR * 2),
                         g_th[(i + 1) & 1] + (row0 + lane) * NSTATE + wid * 256, 512, mb);
            }
        } else {
            __syncthreads();   // last iter: make stage2 visible to epilogue
        }

        if (doD) {   // epilogue: one output element per thread, hidden under TMA
            float s = 0.f;
            #pragma unroll
            for (int w = 0; w < 8; w++) s += redD[w * 512 + tid];
            out[oi0] = s + bo - xv0;
            __syncthreads();   // protect redD from next iteration's stage1
        }
    }
}

extern "C" void kernel_launch(void* const* d_in, const int* in_sizes, int n_in,
                              void* d_out, int out_size) {
    const float* x      = (const float*)d_in[0];
    const float* h_init = (const float*)d_in[1];
    const float* w_r    = (const float*)d_in[2];
    const float* b_r    = (const float*)d_in[3];
    const float* w_o    = (const float*)d_in[4];
    const float* b_o    = (const float*)d_in[5];
    float* out = (float*)d_out;

    static bool configured = false;
    if (!configured) {
        cudaFuncSetAttribute(rnn_scan_kernel,
                             cudaFuncAttributeMaxDynamicSharedMemorySize, SMEM_BYTES);
        configured = true;
    }
    rnn_scan_kernel<<<NCTA, NTHR, SMEM_BYTES>>>(x, h_init, w_r, b_r, w_o, b_o, out);
}

// round 13
// speedup vs baseline: 1.1014x; 1.1014x over previous
#include <cuda_runtime.h>
#include <cuda_bf16.h>
#include <cstdint>

#define SEQ     512
#define NBATCH  256
#define NSTATE  1024
#define NOUT    256
#define ALPHA   0.1f
#define OMALPHA 0.9f

#define NCTA 128
#define NTHR 256

#define WR_STR 1032                 // bf16; 2064B ≡ 16 mod 128 -> conflict-free LDSM
#define WO_STR 1032
#define TH2_STR 72                  // 144B ≡ 16 mod 128 -> conflict-free LDSM
#define CH2_ELEM (32 * TH2_STR)     // 2304 bf16 per producer tile
#define CH2_B    (CH2_ELEM * 2)     // 4608 B

#define SMEM_WR   (64 * WR_STR)
#define SMEM_TH2  (16 * CH2_ELEM)
#define REDD_F    (8 * 512)
#define SMEM_BYTES ((SMEM_WR + SMEM_TH2) * 2 + REDD_F * 4 + 64)

// per-producer padded tiles: [buf][group(8) * producer(16)][32*72]
__device__ __align__(16) __nv_bfloat16 g_th2[2][8 * 16 * CH2_ELEM];
__device__ unsigned g_flags[NCTA * 32];     // one flag per 128B, monotone

__device__ __forceinline__ float tanh_f(float v) {
    float r; asm("tanh.approx.f32 %0, %1;" : "=f"(r) : "f"(v)); return r;
}
__device__ __forceinline__ unsigned pack2(float a, float b) {
    __nv_bfloat162 t = __floats2bfloat162_rn(a, b);
    return *reinterpret_cast<unsigned*>(&t);
}
__device__ __forceinline__ void stcg_u32(void* p, unsigned v) {
    asm volatile("st.global.cg.b32 [%0], %1;" :: "l"(p), "r"(v));
}
__device__ __forceinline__ void ldsm4(unsigned r[4], unsigned addr) {
    asm volatile("ldmatrix.sync.aligned.m8n8.x4.shared.b16 {%0,%1,%2,%3}, [%4];"
                 : "=r"(r[0]), "=r"(r[1]), "=r"(r[2]), "=r"(r[3]) : "r"(addr));
}
__device__ __forceinline__ void mma16816(float c[4], const unsigned a[4], const unsigned b[2]) {
    asm volatile(
        "mma.sync.aligned.m16n8k16.row.col.f32.bf16.bf16.f32 "
        "{%0,%1,%2,%3},{%4,%5,%6,%7},{%8,%9},{%0,%1,%2,%3};"
        : "+f"(c[0]), "+f"(c[1]), "+f"(c[2]), "+f"(c[3])
        : "r"(a[0]), "r"(a[1]), "r"(a[2]), "r"(a[3]), "r"(b[0]), "r"(b[1]));
}
__device__ __forceinline__ void mbar_init(unsigned mbar, unsigned count) {
    asm volatile("mbarrier.init.shared.b64 [%0], %1;" :: "r"(mbar), "r"(count));
}
__device__ __forceinline__ void mbar_expect_tx(unsigned mbar, unsigned bytes) {
    asm volatile("mbarrier.arrive.expect_tx.shared.b64 _, [%0], %1;"
                 :: "r"(mbar), "r"(bytes) : "memory");
}
__device__ __forceinline__ void mbar_wait(unsigned mbar, unsigned parity) {
    asm volatile(
        "{\n\t.reg .pred P1;\n\t"
        "LAB_W_%=:\n\t"
        "mbarrier.try_wait.parity.acquire.cta.shared::cta.b64 P1, [%0], %1, 0x989680;\n\t"
        "@P1 bra LAB_D_%=;\n\t"
        "bra LAB_W_%=;\n\t"
        "LAB_D_%=:\n\t}"
        :: "r"(mbar), "r"(parity) : "memory");
}
__device__ __forceinline__ void bulk_ldg(unsigned dst_smem, const void* src,
                                         unsigned bytes, unsigned mbar) {
    asm volatile(
        "cp.async.bulk.shared::cta.global.mbarrier::complete_tx::bytes [%0], [%1], %2, [%3];"
        :: "r"(dst_smem), "l"(src), "r"(bytes), "r"(mbar) : "memory");
}

__global__ void __launch_bounds__(NTHR, 1)
rnn_scan_kernel(const float* __restrict__ x, const float* __restrict__ h_init,
                const float* __restrict__ w_r, const float* __restrict__ b_r,
                const float* __restrict__ w_o, const float* __restrict__ b_o,
                float* __restrict__ out)
{
    extern __shared__ char smem_raw[];
    __nv_bfloat16* wr_s = (__nv_bfloat16*)smem_raw;
    __nv_bfloat16* th_s = wr_s + SMEM_WR;            // 16 producer chunks (wo staging in prologue)
    float*         redD = (float*)(th_s + SMEM_TH2); // 8 x 512
    unsigned long long* mbars = (unsigned long long*)(redD + REDD_F);   // 4 quad mbarriers
    unsigned*      s_base = (unsigned*)(mbars + 4);

    const int cta = blockIdx.x, tid = threadIdx.x;
    const int wid = tid >> 5, lane = tid & 31;
    const int g = lane >> 2, tg = lane & 3;
    const int grp = cta >> 4;          // 8 independent groups of 16 CTAs (32 batch rows each)
    const int own = cta & 15;          // this CTA's producer slot (64 state cols)
    const int oq  = own >> 2;          // own quad

    const int row0 = grp * 32;
    const int col0 = own * 64;
    const int wm = (wid >> 2) * 16, wn = (wid & 3) * 16;   // 2x4 warp grid, m16n16 tiles
    const int r0g = row0 + wm + g, r1g = r0g + 8;
    const int cbg = col0 + wn + 2 * tg;
    const int nb2 = own * 16;          // output cols of the D tile

    const unsigned th_u32 = (unsigned)__cvta_generic_to_shared(th_s);
    const unsigned wr_u32 = (unsigned)__cvta_generic_to_shared(wr_s);
    const unsigned mb_u32 = (unsigned)__cvta_generic_to_shared(mbars);
    const int l15 = lane & 15, lhi = lane >> 4;
    const unsigned aA_off = ((wm + l15) * TH2_STR + lhi * 8) * 2;
    const unsigned bA_off = ((wn + l15) * WR_STR + lhi * 8) * 2;
    const unsigned aB_off = (l15 * TH2_STR + lhi * 8) * 2;
    const unsigned bB_off = (l15 * WO_STR + lhi * 8) * 2;

    // own-tile element offsets (fragment positions)
    const int o00 = (wm + g) * TH2_STR + wn + 2 * tg;
    const int o10 = o00 + 8 * TH2_STR;
    __nv_bfloat16* th_own = th_s + own * CH2_ELEM;
    const unsigned tile_idx = (unsigned)(grp * 16 + own) * CH2_ELEM;

    // ---- prologue: w_r -> smem ----
    for (int i = tid; i < 64 * 256; i += NTHR) {
        int n = i >> 8, c4 = i & 255;
        float4 v = ((const float4*)(w_r + (col0 + n) * NSTATE))[c4];
        __nv_bfloat16* d = wr_s + n * WR_STR + c4 * 4;
        d[0] = __float2bfloat16(v.x); d[1] = __float2bfloat16(v.y);
        d[2] = __float2bfloat16(v.z); d[3] = __float2bfloat16(v.w);
    }
    // stage w_o in th_s, pull fragments into registers
    for (int i = tid; i < 16 * 256; i += NTHR) {
        int n = i >> 8, c4 = i & 255;
        float4 v = ((const float4*)(w_o + (nb2 + n) * NSTATE))[c4];
        __nv_bfloat16* d = th_s + n * WO_STR + c4 * 4;
        d[0] = __float2bfloat16(v.x); d[1] = __float2bfloat16(v.y);
        d[2] = __float2bfloat16(v.z); d[3] = __float2bfloat16(v.w);
    }
    __syncthreads();
    unsigned bD[32];   // w_o fragments for chunks c = wid and c = wid+8 (4 k-steps each)
    #pragma unroll
    for (int cs = 0; cs < 2; cs++)
        #pragma unroll
        for (int kk = 0; kk < 4; kk++)
            ldsm4(&bD[(cs * 4 + kk) * 4],
                  th_u32 + bB_off + (((wid + cs * 8) * 64) + kk * 16) * 2);
    __syncthreads();

    float br[4] = { b_r[cbg], b_r[cbg + 1], b_r[cbg + 8], b_r[cbg + 9] };
    const float bo = b_o[nb2 + (tid & 15)];
    float h[8];
    h[0] = h_init[r0g * NSTATE + cbg];     h[1] = h_init[r0g * NSTATE + cbg + 1];
    h[2] = h_init[r1g * NSTATE + cbg];     h[3] = h_init[r1g * NSTATE + cbg + 1];
    h[4] = h_init[r0g * NSTATE + cbg + 8]; h[5] = h_init[r0g * NSTATE + cbg + 9];
    h[6] = h_init[r1g * NSTATE + cbg + 8]; h[7] = h_init[r1g * NSTATE + cbg + 9];

    // publish th[0]: own smem chunk + global tile
    {
        unsigned p0 = pack2(tanh_f(h[0]), tanh_f(h[1]));
        unsigned p1 = pack2(tanh_f(h[2]), tanh_f(h[3]));
        unsigned p2 = pack2(tanh_f(h[4]), tanh_f(h[5]));
        unsigned p3 = pack2(tanh_f(h[6]), tanh_f(h[7]));
        *(unsigned*)(th_own + o00)     = p0;
        *(unsigned*)(th_own + o10)     = p1;
        *(unsigned*)(th_own + o00 + 8) = p2;
        *(unsigned*)(th_own + o10 + 8) = p3;
        __nv_bfloat16* gt = g_th2[0] + tile_idx;
        stcg_u32(gt + o00,     p0);
        stcg_u32(gt + o10,     p1);
        stcg_u32(gt + o00 + 8, p2);
        stcg_u32(gt + o10 + 8, p3);
    }

    if (tid == 0) {
        *s_base = g_flags[cta * 32];
        mbar_init(mb_u32,      1);
        mbar_init(mb_u32 + 8,  1);
        mbar_init(mb_u32 + 16, 1);
        mbar_init(mb_u32 + 24, 1);
    }
    __syncthreads();
    const unsigned base = *s_base;
    unsigned par = 0;

    // flag + issue for iteration 0 (th[0])
    if (tid == 0)
        asm volatile("st.release.gpu.global.b32 [%0], %1;"
                     :: "l"(g_flags + cta * 32), "r"(base + 1) : "memory");
    if (wid == 0) {
        if (lane < 16 && lane != own) {
            const unsigned* f = g_flags + (grp * 16 + lane) * 32;
            unsigned v;
            do { asm volatile("ld.acquire.gpu.global.b32 %0, [%1];" : "=r"(v) : "l"(f) : "memory"); }
            while (v < base + 1);
        }
        __syncwarp();
        if (lane < 16 && (lane & 3) == 0) {
            unsigned q = lane >> 2;
            mbar_expect_tx(mb_u32 + q * 8, CH2_B * ((q == (unsigned)oq) ? 3u : 4u));
        }
        __syncwarp();
        if (lane < 16 && lane != own)
            bulk_ldg(th_u32 + lane * CH2_B,
                     g_th2[0] + (grp * 16 + lane) * CH2_ELEM, CH2_B,
                     mb_u32 + (lane >> 2) * 8);
    }

    // ---- barrier-free scan: iter i consumes th[i]; C -> h_{i+1}; D -> err_{i-1} ----
    for (int i = 0; i <= SEQ; i++) {
        const bool doC = (i < SEQ);
        const bool doD = (i > 0);

        float C0[4] = {0,0,0,0}, C1[4] = {0,0,0,0};
        float D[4][4];
        #pragma unroll
        for (int q = 0; q < 4; q++) { D[q][0]=0; D[q][1]=0; D[q][2]=0; D[q][3]=0; }

        float xv0 = 0.f, xv1 = 0.f; int oi0 = 0, oi1 = 0;
        if (doD) {
            oi0 = ((i - 1) * NBATCH + row0 + (tid >> 4)) * NOUT + nb2 + (tid & 15);
            oi1 = oi0 + 16 * NOUT;
            xv0 = __ldg(x + oi0);
            xv1 = __ldg(x + oi1);
        }

        unsigned waited = 0;
        #pragma unroll
        for (int j = 0; j < 16; j++) {
            const int c = (own + j) & 15;
            if (c != own) {
                const int q = c >> 2;
                if (!((waited >> q) & 1)) { mbar_wait(mb_u32 + q * 8, par); waited |= 1u << q; }
            }
            const unsigned cur = th_u32 + c * CH2_B;
            if (doC) {
                const unsigned abase = cur + aA_off;
                const unsigned bbase = wr_u32 + bA_off + c * 128;   // 64 cols * 2B
                #pragma unroll
                for (int kk = 0; kk < 4; kk++) {
                    unsigned a[4], b[4];
                    ldsm4(a, abase + kk * 32);
                    ldsm4(b, bbase + kk * 32);
                    unsigned b0[2] = { b[0], b[2] }, b1[2] = { b[1], b[3] };
                    mma16816(C0, a, b0);
                    mma16816(C1, a, b1);
                }
            }
            if (doD && (c & 7) == wid) {
                const int cs = c >> 3;
                #pragma unroll
                for (int kk = 0; kk < 4; kk++) {
                    unsigned a0[4], a1[4];
                    ldsm4(a0, cur + aB_off + kk * 32);
                    ldsm4(a1, cur + aB_off + kk * 32 + 16 * TH2_STR * 2);
                    const unsigned* b = &bD[(cs * 4 + kk) * 4];
                    unsigned b0[2] = { b[0], b[2] }, b1[2] = { b[1], b[3] };
                    mma16816(D[0], a0, b0);
                    mma16816(D[1], a0, b1);
                    mma16816(D[2], a1, b0);
                    mma16816(D[3], a1, b1);
                }
            }
        }
        par ^= 1;
        __syncthreads();   // (1) all reads of all chunks complete

        if (doD) {         // stage1: park D partials
            float* rw = redD + wid * 512;
            #pragma unroll
            for (int q = 0; q < 4; q++) {
                int mi = q >> 1, ni = q & 1;
                #pragma unroll
                for (int j = 0; j < 4; j++)
                    rw[(mi * 16 + g + ((j >> 1) << 3)) * 16 + ni * 8 + 2 * tg + (j & 1)] = D[q][j];
            }
        }

        if (doC) {         // h update + publish th[i+1]
            #pragma unroll
            for (int j = 0; j < 4; j++) {
                h[j]     = OMALPHA * h[j]     + ALPHA * (C0[j] + br[j & 1]);
                h[4 + j] = OMALPHA * h[4 + j] + ALPHA * (C1[j] + br[2 + (j & 1)]);
            }
            unsigned p0 = pack2(tanh_f(h[0]), tanh_f(h[1]));
            unsigned p1 = pack2(tanh_f(h[2]), tanh_f(h[3]));
            unsigned p2 = pack2(tanh_f(h[4]), tanh_f(h[5]));
            unsigned p3 = pack2(tanh_f(h[6]), tanh_f(h[7]));
            *(unsigned*)(th_own + o00)     = p0;
            *(unsigned*)(th_own + o10)     = p1;
            *(unsigned*)(th_own + o00 + 8) = p2;
            *(unsigned*)(th_own + o10 + 8) = p3;
            __nv_bfloat16* gt = g_th2[(i + 1) & 1] + tile_idx;
            stcg_u32(gt + o00,     p0);
            stcg_u32(gt + o10,     p1);
            stcg_u32(gt + o00 + 8, p2);
            stcg_u32(gt + o10 + 8, p3);
        }
        __syncthreads();   // (2) own smem tile + global stores + stage1 visible

        if (doC) {
            if (tid == 0)
                asm volatile("st.release.gpu.global.b32 [%0], %1;"
                             :: "l"(g_flags + cta * 32), "r"(base + i + 2) : "memory");
            if (wid == 0) {    // poll peers + fire all 15 TMAs; other warps run epilogue
                const unsigned tgt = base + i + 2;
                if (lane < 16 && lane != own) {
                    const unsigned* f = g_flags + (grp * 16 + lane) * 32;
                    unsigned v;
                    do { asm volatile("ld.acquire.gpu.global.b32 %0, [%1];" : "=r"(v) : "l"(f) : "memory"); }
                    while (v < tgt);
                }
                __syncwarp();
                if (lane < 16 && (lane & 3) == 0) {
                    unsigned q = lane >> 2;
                    mbar_expect_tx(mb_u32 + q * 8, CH2_B * ((q == (unsigned)oq) ? 3u : 4u));
                }
                __syncwarp();
                if (lane < 16 && lane != own)
                    bulk_ldg(th_u32 + lane * CH2_B,
                             g_th2[(i + 1) & 1] + (grp * 16 + lane) * CH2_ELEM, CH2_B,
                             mb_u32 + (lane >> 2) * 8);
            }
        }

        if (doD) {         // epilogue: overlaps warp0's poll/issue and next TMA latency
            float s0 = 0.f, s1 = 0.f;
            #pragma unroll
            for (int w = 0; w < 8; w++) {
                s0 += redD[w * 512 + tid];
                s1 += redD[w * 512 + tid + 256];
            }
            out[oi0] = s0 + bo - xv0;
            out[oi1] = s1 + bo - xv1;
        }
    }
}

extern "C" void kernel_launch(void* const* d_in, const int* in_sizes, int n_in,
                              void* d_out, int out_size) {
    const float* x      = (const float*)d_in[0];
    const float* h_init = (const float*)d_in[1];
    const float* w_r    = (const float*)d_in[2];
    const float* b_r    = (const float*)d_in[3];
    const float* w_o    = (const float*)d_in[4];
    const float* b_o    = (const float*)d_in[5];
    float* out = (float*)d_out;

    static bool configured = false;
    if (!configured) {
        cudaFuncSetAttribute(rnn_scan_kernel,
                             cudaFuncAttributeMaxDynamicSharedMemorySize, SMEM_BYTES);
        configured = true;
    }
    rnn_scan_kernel<<<NCTA, NTHR, SMEM_BYTES>>>(x, h_init, w_r, b_r, w_o, b_o, out);
}

// round 14
// speedup vs baseline: 1.1096x; 1.0074x over previous
#include <cuda_runtime.h>
#include <cuda_bf16.h>
#include <cstdint>

#define SEQ     512
#define NBATCH  256
#define NSTATE  1024
#define NOUT    256
#define ALPHA   0.1f
#define OMALPHA 0.9f

#define NCTA 128
#define NTHR 256

#define WR_STR 1032                 // bf16; 2064B ≡ 16 mod 128 -> conflict-free LDSM
#define WO_STR 1032
#define TH2_STR 72                  // 144B ≡ 16 mod 128 -> conflict-free LDSM
#define CH2_ELEM (32 * TH2_STR)     // 2304 bf16 per producer tile
#define CH2_B    (CH2_ELEM * 2)     // 4608 B

#define SMEM_WR   (64 * WR_STR)
#define SMEM_TH2  (16 * CH2_ELEM)
#define REDD_F    (8 * 512)
#define SMEM_BYTES ((SMEM_WR + SMEM_TH2) * 2 + REDD_F * 4 + 64)

// per-producer padded tiles: [buf][group(8) * producer(16)][32*72]
__device__ __align__(16) __nv_bfloat16 g_th2[2][8 * 16 * CH2_ELEM];
__device__ unsigned g_flags[NCTA * 32];     // one flag per 128B, monotone

__device__ __forceinline__ float tanh_f(float v) {
    float r; asm("tanh.approx.f32 %0, %1;" : "=f"(r) : "f"(v)); return r;
}
__device__ __forceinline__ unsigned pack2(float a, float b) {
    __nv_bfloat162 t = __floats2bfloat162_rn(a, b);
    return *reinterpret_cast<unsigned*>(&t);
}
__device__ __forceinline__ void stcg_u32(void* p, unsigned v) {
    asm volatile("st.global.cg.b32 [%0], %1;" :: "l"(p), "r"(v));
}
__device__ __forceinline__ void ldsm4(unsigned r[4], unsigned addr) {
    asm volatile("ldmatrix.sync.aligned.m8n8.x4.shared.b16 {%0,%1,%2,%3}, [%4];"
                 : "=r"(r[0]), "=r"(r[1]), "=r"(r[2]), "=r"(r[3]) : "r"(addr));
}
__device__ __forceinline__ void mma16816(float c[4], const unsigned a[4], const unsigned b[2]) {
    asm volatile(
        "mma.sync.aligned.m16n8k16.row.col.f32.bf16.bf16.f32 "
        "{%0,%1,%2,%3},{%4,%5,%6,%7},{%8,%9},{%0,%1,%2,%3};"
        : "+f"(c[0]), "+f"(c[1]), "+f"(c[2]), "+f"(c[3])
        : "r"(a[0]), "r"(a[1]), "r"(a[2]), "r"(a[3]), "r"(b[0]), "r"(b[1]));
}
__device__ __forceinline__ void mbar_init(unsigned mbar, unsigned count) {
    asm volatile("mbarrier.init.shared.b64 [%0], %1;" :: "r"(mbar), "r"(count));
}
__device__ __forceinline__ void mbar_expect_tx(unsigned mbar, unsigned bytes) {
    asm volatile("mbarrier.arrive.expect_tx.shared.b64 _, [%0], %1;"
                 :: "r"(mbar), "r"(bytes) : "memory");
}
__device__ __forceinline__ void mbar_wait(unsigned mbar, unsigned parity) {
    asm volatile(
        "{\n\t.reg .pred P1;\n\t"
        "LAB_W_%=:\n\t"
        "mbarrier.try_wait.parity.acquire.cta.shared::cta.b64 P1, [%0], %1, 0x989680;\n\t"
        "@P1 bra LAB_D_%=;\n\t"
        "bra LAB_W_%=;\n\t"
        "LAB_D_%=:\n\t}"
        :: "r"(mbar), "r"(parity) : "memory");
}
__device__ __forceinline__ void bulk_ldg(unsigned dst_smem, const void* src,
                                         unsigned bytes, unsigned mbar) {
    asm volatile(
        "cp.async.bulk.shared::cta.global.mbarrier::complete_tx::bytes [%0], [%1], %2, [%3];"
        :: "r"(dst_smem), "l"(src), "r"(bytes), "r"(mbar) : "memory");
}

__global__ void __launch_bounds__(NTHR, 1)
rnn_scan_kernel(const float* __restrict__ x, const float* __restrict__ h_init,
                const float* __restrict__ w_r, const float* __restrict__ b_r,
                const float* __restrict__ w_o, const float* __restrict__ b_o,
                float* __restrict__ out)
{
    extern __shared__ char smem_raw[];
    __nv_bfloat16* wr_s = (__nv_bfloat16*)smem_raw;
    __nv_bfloat16* th_s = wr_s + SMEM_WR;            // 16 producer chunks (wo staging in prologue)
    float*         redD = (float*)(th_s + SMEM_TH2); // 8 x 512
    unsigned long long* mbars = (unsigned long long*)(redD + REDD_F);   // 4 quad mbarriers
    unsigned*      s_base = (unsigned*)(mbars + 4);

    const int cta = blockIdx.x, tid = threadIdx.x;
    const int wid = tid >> 5, lane = tid & 31;
    const int g = lane >> 2, tg = lane & 3;
    const int grp = cta >> 4;          // 8 independent groups of 16 CTAs (32 batch rows each)
    const int own = cta & 15;          // this CTA's producer slot (64 state cols)
    const int oq  = own >> 2;          // own quad

    const int row0 = grp * 32;
    const int col0 = own * 64;
    const int wm = (wid >> 2) * 16, wn = (wid & 3) * 16;   // 2x4 warp grid, m16n16 tiles
    const int r0g = row0 + wm + g, r1g = r0g + 8;
    const int cbg = col0 + wn + 2 * tg;
    const int nb2 = own * 16;          // output cols of the D tile

    const unsigned th_u32 = (unsigned)__cvta_generic_to_shared(th_s);
    const unsigned wr_u32 = (unsigned)__cvta_generic_to_shared(wr_s);
    const unsigned mb_u32 = (unsigned)__cvta_generic_to_shared(mbars);
    const int l15 = lane & 15, lhi = lane >> 4;
    const unsigned aA_off = ((wm + l15) * TH2_STR + lhi * 8) * 2;
    const unsigned bA_off = ((wn + l15) * WR_STR + lhi * 8) * 2;
    const unsigned aB_off = (l15 * TH2_STR + lhi * 8) * 2;
    const unsigned bB_off = (l15 * WO_STR + lhi * 8) * 2;

    const int o00 = (wm + g) * TH2_STR + wn + 2 * tg;
    const int o10 = o00 + 8 * TH2_STR;
    __nv_bfloat16* th_own = th_s + own * CH2_ELEM;
    const unsigned tile_idx = (unsigned)(grp * 16 + own) * CH2_ELEM;

    // ---- prologue: w_r -> smem ----
    for (int i = tid; i < 64 * 256; i += NTHR) {
        int n = i >> 8, c4 = i & 255;
        float4 v = ((const float4*)(w_r + (col0 + n) * NSTATE))[c4];
        __nv_bfloat16* d = wr_s + n * WR_STR + c4 * 4;
        d[0] = __float2bfloat16(v.x); d[1] = __float2bfloat16(v.y);
        d[2] = __float2bfloat16(v.z); d[3] = __float2bfloat16(v.w);
    }
    // stage w_o in th_s, pull fragments into registers
    for (int i = tid; i < 16 * 256; i += NTHR) {
        int n = i >> 8, c4 = i & 255;
        float4 v = ((const float4*)(w_o + (nb2 + n) * NSTATE))[c4];
        __nv_bfloat16* d = th_s + n * WO_STR + c4 * 4;
        d[0] = __float2bfloat16(v.x); d[1] = __float2bfloat16(v.y);
        d[2] = __float2bfloat16(v.z); d[3] = __float2bfloat16(v.w);
    }
    __syncthreads();
    unsigned bD[32];   // w_o fragments for chunks c = wid and c = wid+8
    #pragma unroll
    for (int cs = 0; cs < 2; cs++)
        #pragma unroll
        for (int kk = 0; kk < 4; kk++)
            ldsm4(&bD[(cs * 4 + kk) * 4],
                  th_u32 + bB_off + (((wid + cs * 8) * 64) + kk * 16) * 2);
    __syncthreads();

    float br[4] = { b_r[cbg], b_r[cbg + 1], b_r[cbg + 8], b_r[cbg + 9] };
    const float bo = b_o[nb2 + (tid & 15)];
    float h[8];
    h[0] = h_init[r0g * NSTATE + cbg];     h[1] = h_init[r0g * NSTATE + cbg + 1];
    h[2] = h_init[r1g * NSTATE + cbg];     h[3] = h_init[r1g * NSTATE + cbg + 1];
    h[4] = h_init[r0g * NSTATE + cbg + 8]; h[5] = h_init[r0g * NSTATE + cbg + 9];
    h[6] = h_init[r1g * NSTATE + cbg + 8]; h[7] = h_init[r1g * NSTATE + cbg + 9];

    // publish th[0]: own smem chunk + global tile
    {
        unsigned p0 = pack2(tanh_f(h[0]), tanh_f(h[1]));
        unsigned p1 = pack2(tanh_f(h[2]), tanh_f(h[3]));
        unsigned p2 = pack2(tanh_f(h[4]), tanh_f(h[5]));
        unsigned p3 = pack2(tanh_f(h[6]), tanh_f(h[7]));
        *(unsigned*)(th_own + o00)     = p0;
        *(unsigned*)(th_own + o10)     = p1;
        *(unsigned*)(th_own + o00 + 8) = p2;
        *(unsigned*)(th_own + o10 + 8) = p3;
        __nv_bfloat16* gt = g_th2[0] + tile_idx;
        stcg_u32(gt + o00,     p0);
        stcg_u32(gt + o10,     p1);
        stcg_u32(gt + o00 + 8, p2);
        stcg_u32(gt + o10 + 8, p3);
    }

    if (tid == 0) {
        *s_base = g_flags[cta * 32];
        mbar_init(mb_u32,      1);
        mbar_init(mb_u32 + 8,  1);
        mbar_init(mb_u32 + 16, 1);
        mbar_init(mb_u32 + 24, 1);
    }
    __syncthreads();
    const unsigned base = *s_base;
    unsigned par = 0;

    // flag + issue for iteration 0 (th[0]): per-lane independent poll -> TMA
    if (tid == 0)
        asm volatile("st.release.gpu.global.b32 [%0], %1;"
                     :: "l"(g_flags + cta * 32), "r"(base + 1) : "memory");
    if (wid == 0) {
        if (lane < 4)   // expect_tx upfront (in-order before any TMA issue below)
            mbar_expect_tx(mb_u32 + lane * 8, CH2_B * ((lane == oq) ? 3u : 4u));
        if (lane < 16 && lane != own) {
            const unsigned* f = g_flags + (grp * 16 + lane) * 32;
            unsigned v;
            do { asm volatile("ld.acquire.gpu.global.b32 %0, [%1];" : "=r"(v) : "l"(f) : "memory"); }
            while (v < base + 1);
            bulk_ldg(th_u32 + lane * CH2_B,
                     g_th2[0] + (grp * 16 + lane) * CH2_ELEM, CH2_B,
                     mb_u32 + (lane >> 2) * 8);
        }
    }

    // ---- barrier-free scan: iter i consumes th[i]; C -> h_{i+1}; D -> err_{i-1} ----
    for (int i = 0; i <= SEQ; i++) {
        const bool doC = (i < SEQ);
        const bool doD = (i > 0);

        // 4 independent C accumulator pairs (even/odd k-step) to break RAW chains
        float Ce0[4] = {0,0,0,0}, Ce1[4] = {0,0,0,0};
        float Co0[4] = {0,0,0,0}, Co1[4] = {0,0,0,0};
        float D[4][4];
        #pragma unroll
        for (int q = 0; q < 4; q++) { D[q][0]=0; D[q][1]=0; D[q][2]=0; D[q][3]=0; }

        float xv0 = 0.f, xv1 = 0.f; int oi0 = 0, oi1 = 0;
        if (doD) {
            oi0 = ((i - 1) * NBATCH + row0 + (tid >> 4)) * NOUT + nb2 + (tid & 15);
            oi1 = oi0 + 16 * NOUT;
            xv0 = __ldg(x + oi0);
            xv1 = __ldg(x + oi1);
        }

        unsigned waited = 0;
        #pragma unroll
        for (int j = 0; j < 16; j++) {
            const int c = (own + j) & 15;
            if (c != own) {
                const int q = c >> 2;
                if (!((waited >> q) & 1)) { mbar_wait(mb_u32 + q * 8, par); waited |= 1u << q; }
            }
            const unsigned cur = th_u32 + c * CH2_B;
            if (doC) {
                const unsigned abase = cur + aA_off;
                const unsigned bbase = wr_u32 + bA_off + c * 128;   // 64 cols * 2B
                #pragma unroll
                for (int kk = 0; kk < 4; kk++) {
                    unsigned a[4], b[4];
                    ldsm4(a, abase + kk * 32);
                    ldsm4(b, bbase + kk * 32);
                    unsigned b0[2] = { b[0], b[2] }, b1[2] = { b[1], b[3] };
                    if (kk & 1) { mma16816(Co0, a, b0); mma16816(Co1, a, b1); }
                    else        { mma16816(Ce0, a, b0); mma16816(Ce1, a, b1); }
                }
            }
            if (doD && (c & 7) == wid) {
                const int cs = c >> 3;
                #pragma unroll
                for (int kk = 0; kk < 4; kk++) {
                    unsigned a0[4], a1[4];
                    ldsm4(a0, cur + aB_off + kk * 32);
                    ldsm4(a1, cur + aB_off + kk * 32 + 16 * TH2_STR * 2);
                    const unsigned* b = &bD[(cs * 4 + kk) * 4];
                    unsigned b0[2] = { b[0], b[2] }, b1[2] = { b[1], b[3] };
                    mma16816(D[0], a0, b0);
                    mma16816(D[1], a0, b1);
                    mma16816(D[2], a1, b0);
                    mma16816(D[3], a1, b1);
                }
            }
        }
        par ^= 1;
        __syncthreads();   // (1) all reads of all chunks complete

        if (doD) {         // stage1: park D partials
            float* rw = redD + wid * 512;
            #pragma unroll
            for (int q = 0; q < 4; q++) {
                int mi = q >> 1, ni = q & 1;
                #pragma unroll
                for (int j = 0; j < 4; j++)
                    rw[(mi * 16 + g + ((j >> 1) << 3)) * 16 + ni * 8 + 2 * tg + (j & 1)] = D[q][j];
            }
        }

        if (doC) {         // h update + publish th[i+1]
            #pragma unroll
            for (int j = 0; j < 4; j++) {
                h[j]     = OMALPHA * h[j]     + ALPHA * (Ce0[j] + Co0[j] + br[j & 1]);
                h[4 + j] = OMALPHA * h[4 + j] + ALPHA * (Ce1[j] + Co1[j] + br[2 + (j & 1)]);
            }
            unsigned p0 = pack2(tanh_f(h[0]), tanh_f(h[1]));
            unsigned p1 = pack2(tanh_f(h[2]), tanh_f(h[3]));
            unsigned p2 = pack2(tanh_f(h[4]), tanh_f(h[5]));
            unsigned p3 = pack2(tanh_f(h[6]), tanh_f(h[7]));
            *(unsigned*)(th_own + o00)     = p0;
            *(unsigned*)(th_own + o10)     = p1;
            *(unsigned*)(th_own + o00 + 8) = p2;
            *(unsigned*)(th_own + o10 + 8) = p3;
            __nv_bfloat16* gt = g_th2[(i + 1) & 1] + tile_idx;
            stcg_u32(gt + o00,     p0);
            stcg_u32(gt + o10,     p1);
            stcg_u32(gt + o00 + 8, p2);
            stcg_u32(gt + o10 + 8, p3);
        }
        __syncthreads();   // (2) own smem tile + global stores + stage1 visible

        if (doC) {
            if (tid == 0)
                asm volatile("st.release.gpu.global.b32 [%0], %1;"
                             :: "l"(g_flags + cta * 32), "r"(base + i + 2) : "memory");
            if (wid == 0) {    // per-lane: expect upfront, then poll own peer -> fire TMA
                const unsigned tgt = base + i + 2;
                if (lane < 4)
                    mbar_expect_tx(mb_u32 + lane * 8, CH2_B * ((lane == oq) ? 3u : 4u));
                if (lane < 16 && lane != own) {
                    const unsigned* f = g_flags + (grp * 16 + lane) * 32;
                    unsigned v;
                    do { asm volatile("ld.acquire.gpu.global.b32 %0, [%1];" : "=r"(v) : "l"(f) : "memory"); }
                    while (v < tgt);
                    bulk_ldg(th_u32 + lane * CH2_B,
                             g_th2[(i + 1) & 1] + (grp * 16 + lane) * CH2_ELEM, CH2_B,
                             mb_u32 + (lane >> 2) * 8);
                }
            }
        }

        if (doD) {         // epilogue: overlaps warp0's poll/issue and next TMA latency
            float s0 = 0.f, s1 = 0.f;
            #pragma unroll
            for (int w = 0; w < 8; w++) {
                s0 += redD[w * 512 + tid];
                s1 += redD[w * 512 + tid + 256];
            }
            out[oi0] = s0 + bo - xv0;
            out[oi1] = s1 + bo - xv1;
        }
    }
}

extern "C" void kernel_launch(void* const* d_in, const int* in_sizes, int n_in,
                              void* d_out, int out_size) {
    const float* x      = (const float*)d_in[0];
    const float* h_init = (const float*)d_in[1];
    const float* w_r    = (const float*)d_in[2];
    const float* b_r    = (const float*)d_in[3];
    const float* w_o    = (const float*)d_in[4];
    const float* b_o    = (const float*)d_in[5];
    float* out = (float*)d_out;

    static bool configured = false;
    if (!configured) {
        cudaFuncSetAttribute(rnn_scan_kernel,
                             cudaFuncAttributeMaxDynamicSharedMemorySize, SMEM_BYTES);
        configured = true;
    }
    rnn_scan_kernel<<<NCTA, NTHR, SMEM_BYTES>>>(x, h_init, w_r, b_r, w_o, b_o, out);
}